// round 6
// baseline (speedup 1.0000x reference)
#include <cuda_runtime.h>
#include <cuda_bf16.h>

#define SLEN 2048
#define NH   16
#define HD   64
#define QT   64
#define KT   64
#define STR  72            // bf16 smem row stride (144B)
#define LOG2E 1.4426950408889634f
#define FIXM 12.0f         // fixed softmax shift (log2 domain); cancels in o/l
#define STAGE_BYTES 37120  // KsH(9216)+KsL(9216)+VtH(9216)+VtL(9216)+djs(256)

// Scratch (allocation-free rule: __device__ globals)
__device__ __nv_bfloat16 g_Kh [NH * SLEN * HD];
__device__ __nv_bfloat16 g_Kl [NH * SLEN * HD];
__device__ __nv_bfloat16 g_VtH[NH * HD * SLEN];   // V transposed [h][d][j]
__device__ __nv_bfloat16 g_VtL[NH * HD * SLEN];
__device__ float g_posf[SLEN];
__device__ int   g_nvalid;

// ---- asm helpers ----------------------------------------------------------
__device__ __forceinline__ void mma_bf16(float (&d)[4], const unsigned (&a)[4],
                                         unsigned b0, unsigned b1) {
    asm("mma.sync.aligned.m16n8k16.row.col.f32.bf16.bf16.f32 "
        "{%0,%1,%2,%3}, {%4,%5,%6,%7}, {%8,%9}, {%0,%1,%2,%3};"
        : "+f"(d[0]), "+f"(d[1]), "+f"(d[2]), "+f"(d[3])
        : "r"(a[0]), "r"(a[1]), "r"(a[2]), "r"(a[3]), "r"(b0), "r"(b1));
}
__device__ __forceinline__ void ldsm4(unsigned (&r)[4], unsigned addr) {
    asm volatile("ldmatrix.sync.aligned.m8n8.x4.shared.b16 {%0,%1,%2,%3}, [%4];"
        : "=r"(r[0]), "=r"(r[1]), "=r"(r[2]), "=r"(r[3]) : "r"(addr));
}
__device__ __forceinline__ unsigned smem_u32(const void* p) {
    return (unsigned)__cvta_generic_to_shared(p);
}
__device__ __forceinline__ float ex2(float x) {
    float r; asm("ex2.approx.f32 %0, %1;" : "=f"(r) : "f"(x)); return r;
}
__device__ __forceinline__ void splitpack(float x0, float x1, unsigned& hp, unsigned& lp) {
    asm("cvt.rn.bf16x2.f32 %0, %2, %1;" : "=r"(hp) : "f"(x0), "f"(x1));
    float h0, h1;
    asm("mov.b32 {%0, %1}, %2;" : "=h"(*(unsigned short*)&h0), "=h"(*(unsigned short*)&h1) : "r"(hp));
    // widen bf16 halves to f32 by shifting into the top of a 32-bit word
    unsigned lo16 = hp << 16, hi16 = hp & 0xffff0000u;
    float f0 = __uint_as_float(lo16), f1 = __uint_as_float(hi16);
    float r0 = x0 - f0, r1 = x1 - f1;
    asm("cvt.rn.bf16x2.f32 %0, %2, %1;" : "=r"(lp) : "f"(r0), "f"(r1));
}
__device__ __forceinline__ void cp16(unsigned dst, const void* src) {
    asm volatile("cp.async.cg.shared.global [%0], [%1], 16;" :: "r"(dst), "l"(src));
}
__device__ __forceinline__ void cp_commit() {
    asm volatile("cp.async.commit_group;");
}
template<int N> __device__ __forceinline__ void cp_wait() {
    asm volatile("cp.async.wait_group %0;" :: "n"(N));
}

// ---------------------------------------------------------------------------
// Kernel 1 (prep): per-CTA redundant mask scan (smem) + gather/split K,V.
// ---------------------------------------------------------------------------
__global__ void prep_kernel(const float* __restrict__ K, const float* __restrict__ V,
                            const unsigned char* __restrict__ mask8) {
    __shared__ int   cnt[256];
    __shared__ short s_pos[SLEN];
    __shared__ int   s_n;
    int tid  = threadIdx.x;
    int base = tid * 8;

    int probe = 0;
#pragma unroll
    for (int i = 0; i < 8; i++) {
        int p = base + i;
        if ((p & 3) != 0 && mask8[p] != 0) probe = 1;
    }
    int isU8 = __syncthreads_or(probe);
    const int* mask32 = (const int*)mask8;
    int v[8], c = 0;
#pragma unroll
    for (int i = 0; i < 8; i++) {
        int e = base + i;
        int val = isU8 ? (int)(mask8[e] != 0) : (int)(mask32[e] != 0);
        v[i] = val; c += val;
    }
    cnt[tid] = c;
    __syncthreads();
    for (int off = 1; off < 256; off <<= 1) {
        int t = (tid >= off) ? cnt[tid - off] : 0;
        __syncthreads();
        cnt[tid] += t;
        __syncthreads();
    }
    int idx = cnt[tid] - c;
#pragma unroll
    for (int i = 0; i < 8; i++) {
        if (v[i]) s_pos[idx++] = (short)(base + i);
    }
    if (tid == 255) s_n = cnt[255];
    __syncthreads();
    int n = s_n;

    if (blockIdx.x == 0 && blockIdx.y == 0) {
        for (int j = tid; j < SLEN; j += 256)
            g_posf[j] = (j < n) ? (float)((int)s_pos[j] - (SLEN - 1)) : -1.0e30f;
        if (tid == 0) g_nvalid = n;
    }

    int h   = blockIdx.y;
    int jin = tid & 15;
    int d4  = tid >> 4;
    int j   = blockIdx.x * 16 + jin;
    float4 kk = make_float4(0.f, 0.f, 0.f, 0.f), vv = kk;
    if (j < n) {
        int src = s_pos[j];
        kk = *(const float4*)(K + ((size_t)h * SLEN + src) * HD + d4 * 4);
        vv = *(const float4*)(V + ((size_t)h * SLEN + src) * HD + d4 * 4);
    }
    float ka[4] = {kk.x, kk.y, kk.z, kk.w};
    float va[4] = {vv.x, vv.y, vv.z, vv.w};
    size_t kbase = ((size_t)h * SLEN + j) * HD + 4 * d4;
#pragma unroll
    for (int e = 0; e < 4; e++) {
        __nv_bfloat16 hh = __float2bfloat16(ka[e]);
        __nv_bfloat16 ll = __float2bfloat16(ka[e] - __bfloat162float(hh));
        g_Kh[kbase + e] = hh;
        g_Kl[kbase + e] = ll;
        __nv_bfloat16 vh = __float2bfloat16(va[e]);
        __nv_bfloat16 vl = __float2bfloat16(va[e] - __bfloat162float(vh));
        size_t vt = ((size_t)h * HD + 4 * d4 + e) * SLEN + j;
        g_VtH[vt] = vh;
        g_VtL[vt] = vl;
    }
}

// ---------------------------------------------------------------------------
// prefetch one K/V tile (+djs) into a pipeline stage via cp.async
// ---------------------------------------------------------------------------
__device__ __forceinline__ void prefetch_tile(char* smem, int stage, int h, int k0, int tid) {
    unsigned st = smem_u32(smem + stage * STAGE_BYTES);
    const uint4* gKh = (const uint4*)(g_Kh + ((size_t)h * SLEN + k0) * HD);
    const uint4* gKl = (const uint4*)(g_Kl + ((size_t)h * SLEN + k0) * HD);
#pragma unroll
    for (int i = 0; i < 4; i++) {
        int idx = tid + 128 * i;
        int row = idx >> 3, c = idx & 7;
        unsigned off = (row * STR + 8 * c) * 2;
        cp16(st + off,         gKh + idx);
        cp16(st + 9216 + off,  gKl + idx);
        cp16(st + 18432 + off, (const uint4*)(g_VtH + ((size_t)h * HD + row) * SLEN + k0) + c);
        cp16(st + 27648 + off, (const uint4*)(g_VtL + ((size_t)h * HD + row) * SLEN + k0) + c);
    }
    if (tid < 16) cp16(st + 36864 + tid * 16, (const uint4*)(g_posf + k0) + tid);
}

// ---------------------------------------------------------------------------
// Kernel 2: flash attention, tensor cores, FIXED-shift softmax (no online max,
// no rescale, no in-loop shuffles), 2-stage cp.async pipeline, hoisted Q frags.
// ---------------------------------------------------------------------------
__global__ __launch_bounds__(128, 3) void attn_kernel(const float* __restrict__ Q,
                                                      float* __restrict__ Out) {
    extern __shared__ char smem[];
    int tid  = threadIdx.x;
    int w    = tid >> 5, lane = tid & 31;
    int t4   = lane & 3;
    int g    = lane >> 2;
    int h    = blockIdx.y, q0 = blockIdx.x * QT;
    const float scaleL = 0.125f * LOG2E;
    const float slopeL = exp2f(-0.5f * (float)(h + 1)) * LOG2E;

    int n      = g_nvalid;
    int ntiles = (n + KT - 1) >> 6;

    prefetch_tile(smem, 0, h, 0, tid);
    cp_commit();

    // ---- Q prologue (stage-1 region reused as staging) ----
    __nv_bfloat16* Qh = (__nv_bfloat16*)(smem + STAGE_BYTES);
    __nv_bfloat16* Ql = Qh + QT * STR;
    const float* Qg = Q + ((size_t)h * SLEN + q0) * HD;
    for (int idx = tid; idx < QT * 16; idx += 128) {
        int row = idx >> 4, c4 = idx & 15;
        float4 v = *(const float4*)(Qg + row * HD + c4 * 4);
        unsigned hp0, lp0, hp1, lp1;
        splitpack(v.x * scaleL, v.y * scaleL, hp0, lp0);
        splitpack(v.z * scaleL, v.w * scaleL, hp1, lp1);
        unsigned off = row * STR + 4 * c4;
        *(unsigned*)&Qh[off]     = hp0;
        *(unsigned*)&Qh[off + 2] = hp1;
        *(unsigned*)&Ql[off]     = lp0;
        *(unsigned*)&Ql[off + 2] = lp1;
    }
    __syncthreads();
    unsigned qbH = smem_u32(Qh), qbL = smem_u32(Ql);
    unsigned qoff = ((16 * w + (lane & 15)) * STR + 8 * (lane >> 4)) * 2;
    unsigned qfh[4][4], qfl[4][4];
#pragma unroll
    for (int c = 0; c < 4; c++) {
        ldsm4(qfh[c], qbH + qoff + 32 * c);
        ldsm4(qfl[c], qbL + qoff + 32 * c);
    }
    __syncthreads();   // Q staging free -> stage 1 may be overwritten

    if (ntiles > 1) prefetch_tile(smem, 1, h, KT, tid);
    cp_commit();

    unsigned koff4 = (((lane & 7) + 8 * (lane >> 4)) * STR + 8 * ((lane >> 3) & 1)) * 2;

    float oacc[8][4] = {};
    float lS0 = 0.f, lS1 = 0.f;   // lane-local partial row sums (reduced at end)

    for (int tt = 0; tt < ntiles; ++tt) {
        char* st = smem + (tt & 1) * STAGE_BYTES;
        unsigned kbH = smem_u32(st), kbL = kbH + 9216;
        unsigned vbH = kbH + 18432, vbL = kbH + 27648;
        const float* djs = (const float*)(st + 36864);

        cp_wait<1>();
        __syncthreads();

        // ---- S = Q.K^T (log2 domain), 3-term bf16 ----
        float sacc[8][4];
#pragma unroll
        for (int j = 0; j < 8; j++)
#pragma unroll
            for (int e = 0; e < 4; e++) sacc[j][e] = 0.f;

#pragma unroll
        for (int c = 0; c < 4; c++) {
            unsigned kh[8][2], kl[8][2];
#pragma unroll
            for (int jp = 0; jp < 4; jp++) {
                unsigned r[4];
                unsigned a = koff4 + (jp * 16 * STR + 16 * c) * 2;
                ldsm4(r, kbH + a);
                kh[2 * jp][0] = r[0]; kh[2 * jp][1] = r[1];
                kh[2 * jp + 1][0] = r[2]; kh[2 * jp + 1][1] = r[3];
                ldsm4(r, kbL + a);
                kl[2 * jp][0] = r[0]; kl[2 * jp][1] = r[1];
                kl[2 * jp + 1][0] = r[2]; kl[2 * jp + 1][1] = r[3];
            }
#pragma unroll
            for (int j = 0; j < 8; j++) mma_bf16(sacc[j], qfh[c], kh[j][0], kh[j][1]);
#pragma unroll
            for (int j = 0; j < 8; j++) mma_bf16(sacc[j], qfh[c], kl[j][0], kl[j][1]);
#pragma unroll
            for (int j = 0; j < 8; j++) mma_bf16(sacc[j], qfl[c], kh[j][0], kh[j][1]);
        }

        // ---- fixed-shift softmax: p = exp2(s + bias - FIXM); no max, no rescale ----
#pragma unroll
        for (int j = 0; j < 8; j++) {
            float2 b = *(const float2*)&djs[8 * j + 2 * t4];
            float b0 = fmaf(slopeL, b.x, -FIXM);
            float b1 = fmaf(slopeL, b.y, -FIXM);
            sacc[j][0] = ex2(sacc[j][0] + b0);
            sacc[j][1] = ex2(sacc[j][1] + b1);
            sacc[j][2] = ex2(sacc[j][2] + b0);
            sacc[j][3] = ex2(sacc[j][3] + b1);
            lS0 += sacc[j][0] + sacc[j][1];
            lS1 += sacc[j][2] + sacc[j][3];
        }

        // ---- O += P.V (C->A identity, 3-term bf16) ----
#pragma unroll
        for (int c = 0; c < 4; c++) {
            unsigned ph[4], pl[4];
            splitpack(sacc[2 * c][0],     sacc[2 * c][1],     ph[0], pl[0]);
            splitpack(sacc[2 * c][2],     sacc[2 * c][3],     ph[1], pl[1]);
            splitpack(sacc[2 * c + 1][0], sacc[2 * c + 1][1], ph[2], pl[2]);
            splitpack(sacc[2 * c + 1][2], sacc[2 * c + 1][3], ph[3], pl[3]);
            unsigned vh[8][2], vl[8][2];
#pragma unroll
            for (int jp = 0; jp < 4; jp++) {
                unsigned r[4];
                unsigned a = koff4 + (jp * 16 * STR + 16 * c) * 2;
                ldsm4(r, vbH + a);
                vh[2 * jp][0] = r[0]; vh[2 * jp][1] = r[1];
                vh[2 * jp + 1][0] = r[2]; vh[2 * jp + 1][1] = r[3];
                ldsm4(r, vbL + a);
                vl[2 * jp][0] = r[0]; vl[2 * jp][1] = r[1];
                vl[2 * jp + 1][0] = r[2]; vl[2 * jp + 1][1] = r[3];
            }
#pragma unroll
            for (int dj = 0; dj < 8; dj++) mma_bf16(oacc[dj], ph, vh[dj][0], vh[dj][1]);
#pragma unroll
            for (int dj = 0; dj < 8; dj++) mma_bf16(oacc[dj], ph, vl[dj][0], vl[dj][1]);
#pragma unroll
            for (int dj = 0; dj < 8; dj++) mma_bf16(oacc[dj], pl, vh[dj][0], vh[dj][1]);
        }

        __syncthreads();   // stage fully consumed
        if (tt + 2 < ntiles) prefetch_tile(smem, tt & 1, h, (tt + 2) * KT, tid);
        cp_commit();
    }

    // ---- single end-of-kernel row-sum reduction (quad lanes share rows) ----
    lS0 += __shfl_xor_sync(0xffffffffu, lS0, 1);
    lS0 += __shfl_xor_sync(0xffffffffu, lS0, 2);
    lS1 += __shfl_xor_sync(0xffffffffu, lS1, 1);
    lS1 += __shfl_xor_sync(0xffffffffu, lS1, 2);
    float inv0 = 1.0f / lS0, inv1 = 1.0f / lS1;
    int r0 = q0 + 16 * w + g, r1 = r0 + 8;
    float* O0 = Out + ((size_t)h * SLEN + r0) * HD;
    float* O1 = Out + ((size_t)h * SLEN + r1) * HD;
#pragma unroll
    for (int dj = 0; dj < 8; dj++) {
        int col = 8 * dj + 2 * t4;
        *(float2*)&O0[col] = make_float2(oacc[dj][0] * inv0, oacc[dj][1] * inv0);
        *(float2*)&O1[col] = make_float2(oacc[dj][2] * inv1, oacc[dj][3] * inv1);
    }
}

// ---------------------------------------------------------------------------
extern "C" void kernel_launch(void* const* d_in, const int* in_sizes, int n_in,
                              void* d_out, int out_size) {
    const float*         Q    = (const float*)d_in[0];
    const float*         K    = (const float*)d_in[1];
    const float*         V    = (const float*)d_in[2];
    const unsigned char* mask = (const unsigned char*)d_in[3];
    float*               out  = (float*)d_out;

    const int SMEM_BYTES = 2 * STAGE_BYTES;   // 74240
    cudaFuncSetAttribute(attn_kernel, cudaFuncAttributeMaxDynamicSharedMemorySize, SMEM_BYTES);

    dim3 gp(SLEN / 16, NH);
    prep_kernel<<<gp, 256>>>(K, V, mask);
    dim3 ga(SLEN / QT, NH);
    attn_kernel<<<ga, 128, SMEM_BYTES>>>(Q, out);
}

// round 7
// speedup vs baseline: 1.4545x; 1.4545x over previous
#include <cuda_runtime.h>
#include <cuda_bf16.h>

#define SLEN 2048
#define NH   16
#define HD   64
#define QT   64
#define KT   64
#define STR  72            // bf16 smem row stride (144B)
#define LOG2E 1.4426950408889634f
#define FIXM 12.0f         // fixed softmax shift (log2 domain); cancels in o/l
#define STAGE_BYTES 37120  // KsH(9216)+KsL(9216)+VtH(9216)+VtL(9216)+djs(256)

// Scratch (allocation-free rule: __device__ globals)
__device__ __nv_bfloat16 g_Kh [NH * SLEN * HD];
__device__ __nv_bfloat16 g_Kl [NH * SLEN * HD];
__device__ __nv_bfloat16 g_VtH[NH * HD * SLEN];   // V transposed [h][d][j]
__device__ __nv_bfloat16 g_VtL[NH * HD * SLEN];
__device__ float g_posf[SLEN];
__device__ int   g_pos [SLEN];
__device__ int   g_nvalid;

// ---- asm helpers ----------------------------------------------------------
__device__ __forceinline__ void mma_bf16(float (&d)[4], const unsigned (&a)[4],
                                         unsigned b0, unsigned b1) {
    asm("mma.sync.aligned.m16n8k16.row.col.f32.bf16.bf16.f32 "
        "{%0,%1,%2,%3}, {%4,%5,%6,%7}, {%8,%9}, {%0,%1,%2,%3};"
        : "+f"(d[0]), "+f"(d[1]), "+f"(d[2]), "+f"(d[3])
        : "r"(a[0]), "r"(a[1]), "r"(a[2]), "r"(a[3]), "r"(b0), "r"(b1));
}
__device__ __forceinline__ void ldsm4(unsigned (&r)[4], unsigned addr) {
    asm volatile("ldmatrix.sync.aligned.m8n8.x4.shared.b16 {%0,%1,%2,%3}, [%4];"
        : "=r"(r[0]), "=r"(r[1]), "=r"(r[2]), "=r"(r[3]) : "r"(addr));
}
__device__ __forceinline__ unsigned smem_u32(const void* p) {
    return (unsigned)__cvta_generic_to_shared(p);
}
__device__ __forceinline__ float ex2(float x) {
    float r; asm("ex2.approx.f32 %0, %1;" : "=f"(r) : "f"(x)); return r;
}
__device__ __forceinline__ void splitpack(float x0, float x1, unsigned& hp, unsigned& lp) {
    __nv_bfloat16 h0 = __float2bfloat16(x0), h1 = __float2bfloat16(x1);
    float r0 = x0 - __bfloat162float(h0), r1 = x1 - __bfloat162float(h1);
    __nv_bfloat16 l0 = __float2bfloat16(r0), l1 = __float2bfloat16(r1);
    hp = ((unsigned)__bfloat16_as_ushort(h1) << 16) | (unsigned)__bfloat16_as_ushort(h0);
    lp = ((unsigned)__bfloat16_as_ushort(l1) << 16) | (unsigned)__bfloat16_as_ushort(l0);
}
__device__ __forceinline__ void cp16(unsigned dst, const void* src) {
    asm volatile("cp.async.cg.shared.global [%0], [%1], 16;" :: "r"(dst), "l"(src));
}
__device__ __forceinline__ void cp_commit() {
    asm volatile("cp.async.commit_group;");
}
template<int N> __device__ __forceinline__ void cp_wait() {
    asm volatile("cp.async.wait_group %0;" :: "n"(N));
}

// ---------------------------------------------------------------------------
// Kernel 1: mask compaction, single CTA, shfl-scan (3 barriers total).
// Mask layout auto-detect (u8 vs int32-widened numpy bool).
// ---------------------------------------------------------------------------
__global__ void compact_kernel(const unsigned char* __restrict__ mask8) {
    __shared__ int warpSum[8];
    int tid  = threadIdx.x;
    int lane = tid & 31, wid = tid >> 5;
    int base = tid * 8;

    int probe = 0;
#pragma unroll
    for (int i = 0; i < 8; i++) {
        int p = base + i;
        if ((p & 3) != 0 && mask8[p] != 0) probe = 1;
    }
    int isU8 = __syncthreads_or(probe);
    const int* mask32 = (const int*)mask8;
    int v[8], c = 0;
#pragma unroll
    for (int i = 0; i < 8; i++) {
        int e = base + i;
        int val = isU8 ? (int)(mask8[e] != 0) : (int)(mask32[e] != 0);
        v[i] = val; c += val;
    }
    // warp inclusive scan of per-thread counts
    int incl = c;
#pragma unroll
    for (int off = 1; off < 32; off <<= 1) {
        int t = __shfl_up_sync(0xffffffffu, incl, off);
        if (lane >= off) incl += t;
    }
    if (lane == 31) warpSum[wid] = incl;
    __syncthreads();
    if (wid == 0) {
        int ws = (lane < 8) ? warpSum[lane] : 0;
#pragma unroll
        for (int off = 1; off < 8; off <<= 1) {
            int t = __shfl_up_sync(0xffffffffu, ws, off);
            if (lane >= off) ws += t;
        }
        if (lane < 8) warpSum[lane] = ws;
    }
    __syncthreads();
    int wbase = (wid > 0) ? warpSum[wid - 1] : 0;
    int idx = wbase + incl - c;     // exclusive prefix
#pragma unroll
    for (int i = 0; i < 8; i++) {
        if (v[i]) {
            g_pos [idx] = base + i;
            g_posf[idx] = (float)(base + i - (SLEN - 1));
            idx++;
        }
    }
    int n = warpSum[7];
    for (int j = n + tid; j < SLEN; j += 256) g_posf[j] = -1.0e30f;
    if (tid == 0) g_nvalid = n;
}

// ---------------------------------------------------------------------------
// Kernel 2: gather + fp32->bf16 hi/lo split (no scan; reads g_pos from L2).
// ---------------------------------------------------------------------------
__global__ void scatter_kernel(const float* __restrict__ K, const float* __restrict__ V) {
    int h   = blockIdx.y;
    int jin = threadIdx.x & 15;
    int d4  = threadIdx.x >> 4;
    int j   = blockIdx.x * 16 + jin;
    int n   = g_nvalid;
    float4 kk = make_float4(0.f, 0.f, 0.f, 0.f), vv = kk;
    if (j < n) {
        int src = g_pos[j];
        kk = *(const float4*)(K + ((size_t)h * SLEN + src) * HD + d4 * 4);
        vv = *(const float4*)(V + ((size_t)h * SLEN + src) * HD + d4 * 4);
    }
    float ka[4] = {kk.x, kk.y, kk.z, kk.w};
    float va[4] = {vv.x, vv.y, vv.z, vv.w};
    size_t kbase = ((size_t)h * SLEN + j) * HD + 4 * d4;
#pragma unroll
    for (int e = 0; e < 4; e++) {
        __nv_bfloat16 hh = __float2bfloat16(ka[e]);
        __nv_bfloat16 ll = __float2bfloat16(ka[e] - __bfloat162float(hh));
        g_Kh[kbase + e] = hh;
        g_Kl[kbase + e] = ll;
        __nv_bfloat16 vh = __float2bfloat16(va[e]);
        __nv_bfloat16 vl = __float2bfloat16(va[e] - __bfloat162float(vh));
        size_t vt = ((size_t)h * HD + 4 * d4 + e) * SLEN + j;
        g_VtH[vt] = vh;
        g_VtL[vt] = vl;
    }
}

// ---------------------------------------------------------------------------
// prefetch one K/V tile (+djs) into a pipeline stage via cp.async
// ---------------------------------------------------------------------------
__device__ __forceinline__ void prefetch_tile(char* smem, int stage, int h, int k0, int tid) {
    unsigned st = smem_u32(smem + stage * STAGE_BYTES);
    const uint4* gKh = (const uint4*)(g_Kh + ((size_t)h * SLEN + k0) * HD);
    const uint4* gKl = (const uint4*)(g_Kl + ((size_t)h * SLEN + k0) * HD);
#pragma unroll
    for (int i = 0; i < 4; i++) {
        int idx = tid + 128 * i;
        int row = idx >> 3, c = idx & 7;
        unsigned off = (row * STR + 8 * c) * 2;
        cp16(st + off,         gKh + idx);
        cp16(st + 9216 + off,  gKl + idx);
        cp16(st + 18432 + off, (const uint4*)(g_VtH + ((size_t)h * HD + row) * SLEN + k0) + c);
        cp16(st + 27648 + off, (const uint4*)(g_VtL + ((size_t)h * HD + row) * SLEN + k0) + c);
    }
    if (tid < 16) cp16(st + 36864 + tid * 16, (const uint4*)(g_posf + k0) + tid);
}

// ---------------------------------------------------------------------------
// Kernel 3: flash attention, tensor cores, fixed-shift softmax, 2-stage
// cp.async pipeline, hoisted Q fragments.
// ---------------------------------------------------------------------------
__global__ __launch_bounds__(128, 3) void attn_kernel(const float* __restrict__ Q,
                                                      float* __restrict__ Out) {
    extern __shared__ char smem[];
    int tid  = threadIdx.x;
    int w    = tid >> 5, lane = tid & 31;
    int t4   = lane & 3;
    int g    = lane >> 2;
    int h    = blockIdx.y, q0 = blockIdx.x * QT;
    const float scaleL = 0.125f * LOG2E;
    const float slopeL = exp2f(-0.5f * (float)(h + 1)) * LOG2E;

    int n      = g_nvalid;
    int ntiles = (n + KT - 1) >> 6;

    prefetch_tile(smem, 0, h, 0, tid);
    cp_commit();

    // ---- Q prologue (stage-1 region reused as staging) ----
    __nv_bfloat16* Qh = (__nv_bfloat16*)(smem + STAGE_BYTES);
    __nv_bfloat16* Ql = Qh + QT * STR;
    const float* Qg = Q + ((size_t)h * SLEN + q0) * HD;
    for (int idx = tid; idx < QT * 16; idx += 128) {
        int row = idx >> 4, c4 = idx & 15;
        float4 v = *(const float4*)(Qg + row * HD + c4 * 4);
        unsigned hp0, lp0, hp1, lp1;
        splitpack(v.x * scaleL, v.y * scaleL, hp0, lp0);
        splitpack(v.z * scaleL, v.w * scaleL, hp1, lp1);
        unsigned off = row * STR + 4 * c4;
        *(unsigned*)&Qh[off]     = hp0;
        *(unsigned*)&Qh[off + 2] = hp1;
        *(unsigned*)&Ql[off]     = lp0;
        *(unsigned*)&Ql[off + 2] = lp1;
    }
    __syncthreads();
    unsigned qbH = smem_u32(Qh), qbL = smem_u32(Ql);
    unsigned qoff = ((16 * w + (lane & 15)) * STR + 8 * (lane >> 4)) * 2;
    unsigned qfh[4][4], qfl[4][4];
#pragma unroll
    for (int c = 0; c < 4; c++) {
        ldsm4(qfh[c], qbH + qoff + 32 * c);
        ldsm4(qfl[c], qbL + qoff + 32 * c);
    }
    __syncthreads();   // Q staging free -> stage 1 may be overwritten

    if (ntiles > 1) prefetch_tile(smem, 1, h, KT, tid);
    cp_commit();

    unsigned koff4 = (((lane & 7) + 8 * (lane >> 4)) * STR + 8 * ((lane >> 3) & 1)) * 2;

    float oacc[8][4] = {};
    float lS0 = 0.f, lS1 = 0.f;   // lane-local partial row sums

    for (int tt = 0; tt < ntiles; ++tt) {
        char* st = smem + (tt & 1) * STAGE_BYTES;
        unsigned kbH = smem_u32(st), kbL = kbH + 9216;
        unsigned vbH = kbH + 18432, vbL = kbH + 27648;
        const float* djs = (const float*)(st + 36864);

        cp_wait<1>();
        __syncthreads();

        // ---- S = Q.K^T (log2 domain), 3-term bf16 ----
        float sacc[8][4];
#pragma unroll
        for (int j = 0; j < 8; j++)
#pragma unroll
            for (int e = 0; e < 4; e++) sacc[j][e] = 0.f;

#pragma unroll
        for (int c = 0; c < 4; c++) {
            unsigned kh[8][2], kl[8][2];
#pragma unroll
            for (int jp = 0; jp < 4; jp++) {
                unsigned r[4];
                unsigned a = koff4 + (jp * 16 * STR + 16 * c) * 2;
                ldsm4(r, kbH + a);
                kh[2 * jp][0] = r[0]; kh[2 * jp][1] = r[1];
                kh[2 * jp + 1][0] = r[2]; kh[2 * jp + 1][1] = r[3];
                ldsm4(r, kbL + a);
                kl[2 * jp][0] = r[0]; kl[2 * jp][1] = r[1];
                kl[2 * jp + 1][0] = r[2]; kl[2 * jp + 1][1] = r[3];
            }
#pragma unroll
            for (int j = 0; j < 8; j++) mma_bf16(sacc[j], qfh[c], kh[j][0], kh[j][1]);
#pragma unroll
            for (int j = 0; j < 8; j++) mma_bf16(sacc[j], qfh[c], kl[j][0], kl[j][1]);
#pragma unroll
            for (int j = 0; j < 8; j++) mma_bf16(sacc[j], qfl[c], kh[j][0], kh[j][1]);
        }

        // ---- fixed-shift softmax: p = exp2(s + bias - FIXM) ----
#pragma unroll
        for (int j = 0; j < 8; j++) {
            float2 b = *(const float2*)&djs[8 * j + 2 * t4];
            float b0 = fmaf(slopeL, b.x, -FIXM);
            float b1 = fmaf(slopeL, b.y, -FIXM);
            sacc[j][0] = ex2(sacc[j][0] + b0);
            sacc[j][1] = ex2(sacc[j][1] + b1);
            sacc[j][2] = ex2(sacc[j][2] + b0);
            sacc[j][3] = ex2(sacc[j][3] + b1);
            lS0 += sacc[j][0] + sacc[j][1];
            lS1 += sacc[j][2] + sacc[j][3];
        }

        // ---- O += P.V (C->A identity, 3-term bf16) ----
#pragma unroll
        for (int c = 0; c < 4; c++) {
            unsigned ph[4], pl[4];
            splitpack(sacc[2 * c][0],     sacc[2 * c][1],     ph[0], pl[0]);
            splitpack(sacc[2 * c][2],     sacc[2 * c][3],     ph[1], pl[1]);
            splitpack(sacc[2 * c + 1][0], sacc[2 * c + 1][1], ph[2], pl[2]);
            splitpack(sacc[2 * c + 1][2], sacc[2 * c + 1][3], ph[3], pl[3]);
            unsigned vh[8][2], vl[8][2];
#pragma unroll
            for (int jp = 0; jp < 4; jp++) {
                unsigned r[4];
                unsigned a = koff4 + (jp * 16 * STR + 16 * c) * 2;
                ldsm4(r, vbH + a);
                vh[2 * jp][0] = r[0]; vh[2 * jp][1] = r[1];
                vh[2 * jp + 1][0] = r[2]; vh[2 * jp + 1][1] = r[3];
                ldsm4(r, vbL + a);
                vl[2 * jp][0] = r[0]; vl[2 * jp][1] = r[1];
                vl[2 * jp + 1][0] = r[2]; vl[2 * jp + 1][1] = r[3];
            }
#pragma unroll
            for (int dj = 0; dj < 8; dj++) mma_bf16(oacc[dj], ph, vh[dj][0], vh[dj][1]);
#pragma unroll
            for (int dj = 0; dj < 8; dj++) mma_bf16(oacc[dj], ph, vl[dj][0], vl[dj][1]);
#pragma unroll
            for (int dj = 0; dj < 8; dj++) mma_bf16(oacc[dj], pl, vh[dj][0], vh[dj][1]);
        }

        __syncthreads();   // stage fully consumed
        if (tt + 2 < ntiles) prefetch_tile(smem, tt & 1, h, (tt + 2) * KT, tid);
        cp_commit();
    }

    // ---- single end-of-kernel row-sum reduction ----
    lS0 += __shfl_xor_sync(0xffffffffu, lS0, 1);
    lS0 += __shfl_xor_sync(0xffffffffu, lS0, 2);
    lS1 += __shfl_xor_sync(0xffffffffu, lS1, 1);
    lS1 += __shfl_xor_sync(0xffffffffu, lS1, 2);
    float inv0 = 1.0f / lS0, inv1 = 1.0f / lS1;
    int r0 = q0 + 16 * w + g, r1 = r0 + 8;
    float* O0 = Out + ((size_t)h * SLEN + r0) * HD;
    float* O1 = Out + ((size_t)h * SLEN + r1) * HD;
#pragma unroll
    for (int dj = 0; dj < 8; dj++) {
        int col = 8 * dj + 2 * t4;
        *(float2*)&O0[col] = make_float2(oacc[dj][0] * inv0, oacc[dj][1] * inv0);
        *(float2*)&O1[col] = make_float2(oacc[dj][2] * inv1, oacc[dj][3] * inv1);
    }
}

// ---------------------------------------------------------------------------
extern "C" void kernel_launch(void* const* d_in, const int* in_sizes, int n_in,
                              void* d_out, int out_size) {
    const float*         Q    = (const float*)d_in[0];
    const float*         K    = (const float*)d_in[1];
    const float*         V    = (const float*)d_in[2];
    const unsigned char* mask = (const unsigned char*)d_in[3];
    float*               out  = (float*)d_out;

    const int SMEM_BYTES = 2 * STAGE_BYTES;   // 74240
    cudaFuncSetAttribute(attn_kernel, cudaFuncAttributeMaxDynamicSharedMemorySize, SMEM_BYTES);

    compact_kernel<<<1, 256>>>(mask);
    dim3 gs(SLEN / 16, NH);
    scatter_kernel<<<gs, 256>>>(K, V);
    dim3 ga(SLEN / QT, NH);
    attn_kernel<<<ga, 128, SMEM_BYTES>>>(Q, out);
}

// round 12
// speedup vs baseline: 1.5908x; 1.0938x over previous
#include <cuda_runtime.h>
#include <cuda_bf16.h>

#define SLEN 2048
#define NH   16
#define HD   64
#define QT   64
#define KT   32
#define LOG2E 1.4426950408889634f
#define FIXM 12.0f

// smem stage layout (KT=32): K tiles 32x72 bf16, V^T tiles 64x40 bf16
#define STRK 72
#define STRV 40
#define OFF_KH 0
#define OFF_KL 4608
#define OFF_VH 9216
#define OFF_VL 14336
#define OFF_DJ 19456
#define STAGE  19584
#define SMEM_BYTES (2 * STAGE)   // 39168 -> 4 CTAs/SM

// Scratch (allocation-free rule) — layouts identical to R7
__device__ __nv_bfloat16 g_Kh [NH * SLEN * HD];   // K rows [h][j][d], hi
__device__ __nv_bfloat16 g_Kl [NH * SLEN * HD];
__device__ __nv_bfloat16 g_VtH[NH * HD * SLEN];   // V transposed [h][d][j]
__device__ __nv_bfloat16 g_VtL[NH * HD * SLEN];
__device__ float g_posf[SLEN];
__device__ int   g_pos [SLEN];
__device__ int   g_nvalid;

// ---- helpers ----------------------------------------------------------------
__device__ __forceinline__ unsigned smem_u32(const void* p) {
    return (unsigned)__cvta_generic_to_shared(p);
}
__device__ __forceinline__ float ex2(float x) {
    float r; asm("ex2.approx.f32 %0, %1;" : "=f"(r) : "f"(x)); return r;
}
__device__ __forceinline__ void splitpack(float x0, float x1, unsigned& hp, unsigned& lp) {
    __nv_bfloat16 h0 = __float2bfloat16(x0), h1 = __float2bfloat16(x1);
    float r0 = x0 - __bfloat162float(h0), r1 = x1 - __bfloat162float(h1);
    __nv_bfloat16 l0 = __float2bfloat16(r0), l1 = __float2bfloat16(r1);
    hp = ((unsigned)__bfloat16_as_ushort(h1) << 16) | (unsigned)__bfloat16_as_ushort(h0);
    lp = ((unsigned)__bfloat16_as_ushort(l1) << 16) | (unsigned)__bfloat16_as_ushort(l0);
}
__device__ __forceinline__ void cp16(unsigned dst, const void* src) {
    asm volatile("cp.async.cg.shared.global [%0], [%1], 16;" :: "r"(dst), "l"(src));
}
__device__ __forceinline__ void cp_commit() { asm volatile("cp.async.commit_group;"); }
template<int N> __device__ __forceinline__ void cp_wait() {
    asm volatile("cp.async.wait_group %0;" :: "n"(N));
}
__device__ __forceinline__ void mma_bf16(float (&d)[4], const unsigned (&a)[4],
                                         unsigned b0, unsigned b1) {
    asm("mma.sync.aligned.m16n8k16.row.col.f32.bf16.bf16.f32 "
        "{%0,%1,%2,%3}, {%4,%5,%6,%7}, {%8,%9}, {%0,%1,%2,%3};"
        : "+f"(d[0]), "+f"(d[1]), "+f"(d[2]), "+f"(d[3])
        : "r"(a[0]), "r"(a[1]), "r"(a[2]), "r"(a[3]), "r"(b0), "r"(b1));
}
__device__ __forceinline__ void ldsm4(unsigned (&r)[4], unsigned addr) {
    asm volatile("ldmatrix.sync.aligned.m8n8.x4.shared.b16 {%0,%1,%2,%3}, [%4];"
        : "=r"(r[0]), "=r"(r[1]), "=r"(r[2]), "=r"(r[3]) : "r"(addr));
}

// ---------------------------------------------------------------------------
// Kernel 1: mask compaction (unchanged — proven)
// ---------------------------------------------------------------------------
__global__ void compact_kernel(const unsigned char* __restrict__ mask8) {
    __shared__ int warpSum[8];
    int tid  = threadIdx.x;
    int lane = tid & 31, wid = tid >> 5;
    int base = tid * 8;
    int probe = 0;
#pragma unroll
    for (int i = 0; i < 8; i++) {
        int p = base + i;
        if ((p & 3) != 0 && mask8[p] != 0) probe = 1;
    }
    int isU8 = __syncthreads_or(probe);
    const int* mask32 = (const int*)mask8;
    int v[8], c = 0;
#pragma unroll
    for (int i = 0; i < 8; i++) {
        int e = base + i;
        int val = isU8 ? (int)(mask8[e] != 0) : (int)(mask32[e] != 0);
        v[i] = val; c += val;
    }
    int incl = c;
#pragma unroll
    for (int off = 1; off < 32; off <<= 1) {
        int t = __shfl_up_sync(0xffffffffu, incl, off);
        if (lane >= off) incl += t;
    }
    if (lane == 31) warpSum[wid] = incl;
    __syncthreads();
    if (wid == 0) {
        int ws = (lane < 8) ? warpSum[lane] : 0;
#pragma unroll
        for (int off = 1; off < 8; off <<= 1) {
            int t = __shfl_up_sync(0xffffffffu, ws, off);
            if (lane >= off) ws += t;
        }
        if (lane < 8) warpSum[lane] = ws;
    }
    __syncthreads();
    int wbase = (wid > 0) ? warpSum[wid - 1] : 0;
    int idx = wbase + incl - c;
#pragma unroll
    for (int i = 0; i < 8; i++) {
        if (v[i]) {
            g_pos [idx] = base + i;
            g_posf[idx] = (float)(base + i - (SLEN - 1));
            idx++;
        }
    }
    int n = warpSum[7];
    for (int j = n + tid; j < SLEN; j += 256) g_posf[j] = -1.0e30f;
    if (tid == 0) g_nvalid = n;
}

// ---------------------------------------------------------------------------
// Kernel 2: gather + hi/lo split (unchanged — proven)
// ---------------------------------------------------------------------------
__global__ void scatter_kernel(const float* __restrict__ K, const float* __restrict__ V) {
    int h   = blockIdx.y;
    int jin = threadIdx.x & 15;
    int d4  = threadIdx.x >> 4;
    int j   = blockIdx.x * 16 + jin;
    int n   = g_nvalid;
    float4 kk = make_float4(0.f, 0.f, 0.f, 0.f), vv = kk;
    if (j < n) {
        int src = g_pos[j];
        kk = *(const float4*)(K + ((size_t)h * SLEN + src) * HD + d4 * 4);
        vv = *(const float4*)(V + ((size_t)h * SLEN + src) * HD + d4 * 4);
    }
    float ka[4] = {kk.x, kk.y, kk.z, kk.w};
    float va[4] = {vv.x, vv.y, vv.z, vv.w};
    size_t kbase = ((size_t)h * SLEN + j) * HD + 4 * d4;
#pragma unroll
    for (int e = 0; e < 4; e++) {
        __nv_bfloat16 hh = __float2bfloat16(ka[e]);
        __nv_bfloat16 ll = __float2bfloat16(ka[e] - __bfloat162float(hh));
        g_Kh[kbase + e] = hh;
        g_Kl[kbase + e] = ll;
        __nv_bfloat16 vh = __float2bfloat16(va[e]);
        __nv_bfloat16 vl = __float2bfloat16(va[e] - __bfloat162float(vh));
        size_t vt = ((size_t)h * HD + 4 * d4 + e) * SLEN + j;
        g_VtH[vt] = vh;
        g_VtL[vt] = vl;
    }
}

// ---------------------------------------------------------------------------
// prefetch one KT=32 K/V tile (+djs) into a stage via cp.async
// K tile:  32 rows(j) x 64 bf16(d) = 256 16B chunks, row stride STRK=72 (144B)
// V tile:  64 rows(d) x 32 bf16(j) = 256 16B chunks, row stride STRV=40 (80B)
// ---------------------------------------------------------------------------
__device__ __forceinline__ void prefetch_tile(char* smem, int stage, int h, int k0, int tid) {
    unsigned st = smem_u32(smem + stage * STAGE);
    const char* bKh = (const char*)(g_Kh + ((size_t)h * SLEN + k0) * HD);
    const char* bKl = (const char*)(g_Kl + ((size_t)h * SLEN + k0) * HD);
#pragma unroll
    for (int i = 0; i < 2; i++) {   // K hi/lo: 256 chunks each (8 chunks per 128B row)
        int idx = tid + 128 * i;
        int row = idx >> 3, c = idx & 7;
        unsigned off = row * (STRK * 2) + c * 16;
        cp16(st + OFF_KH + off, bKh + idx * 16);
        cp16(st + OFF_KL + off, bKl + idx * 16);
    }
#pragma unroll
    for (int i = 0; i < 2; i++) {   // V hi/lo: 256 chunks each (4 chunks per 64B row)
        int idx = tid + 128 * i;
        int row = idx >> 2, c = idx & 3;
        unsigned off = row * (STRV * 2) + c * 16;
        cp16(st + OFF_VH + off, (const char*)(g_VtH + ((size_t)h * HD + row) * SLEN + k0) + c * 16);
        cp16(st + OFF_VL + off, (const char*)(g_VtL + ((size_t)h * HD + row) * SLEN + k0) + c * 16);
    }
    if (tid < 8) cp16(st + OFF_DJ + tid * 16, (const char*)(g_posf + k0) + tid * 16);
}

// ---------------------------------------------------------------------------
// Kernel 3: flash attention, mma.sync, KT=32 tiles, 4 CTAs/SM, single wave.
// 128 threads = 4 warps; warp w owns q rows 16w..16w+15, full KT per tile.
// ---------------------------------------------------------------------------
__global__ __launch_bounds__(128, 4) void attn_kernel(const float* __restrict__ Q,
                                                      float* __restrict__ Out) {
    extern __shared__ char smem[];
    int tid = threadIdx.x, w = tid >> 5, lane = tid & 31;
    int t4 = lane & 3, g = lane >> 2;
    int h = blockIdx.y, q0 = blockIdx.x * QT;
    const float scaleL = 0.125f * LOG2E;
    const float slopeL = exp2f(-0.5f * (float)(h + 1)) * LOG2E;
    int n = g_nvalid, ntiles = (n + KT - 1) >> 5;

    prefetch_tile(smem, 0, h, 0, tid);
    cp_commit();

    // ---- Q prologue (staged in stage-1 region, then freed) ----
    __nv_bfloat16* Qh = (__nv_bfloat16*)(smem + STAGE);
    __nv_bfloat16* Ql = Qh + QT * STRK;
    const float* Qg = Q + ((size_t)h * SLEN + q0) * HD;
    for (int idx = tid; idx < QT * 16; idx += 128) {
        int row = idx >> 4, c4 = idx & 15;
        float4 v = *(const float4*)(Qg + row * HD + c4 * 4);
        unsigned hp0, lp0, hp1, lp1;
        splitpack(v.x * scaleL, v.y * scaleL, hp0, lp0);
        splitpack(v.z * scaleL, v.w * scaleL, hp1, lp1);
        unsigned off = row * STRK + 4 * c4;
        *(unsigned*)&Qh[off]     = hp0;
        *(unsigned*)&Qh[off + 2] = hp1;
        *(unsigned*)&Ql[off]     = lp0;
        *(unsigned*)&Ql[off + 2] = lp1;
    }
    __syncthreads();
    unsigned qbH = smem_u32(Qh), qbL = smem_u32(Ql);
    unsigned qoff = ((16 * w + (lane & 15)) * STRK + 8 * (lane >> 4)) * 2;
    unsigned qfh[4][4], qfl[4][4];
#pragma unroll
    for (int c = 0; c < 4; c++) {
        ldsm4(qfh[c], qbH + qoff + 32 * c);
        ldsm4(qfl[c], qbL + qoff + 32 * c);
    }
    __syncthreads();   // Q staging free -> stage 1 may be overwritten

    if (ntiles > 1) prefetch_tile(smem, 1, h, KT, tid);
    cp_commit();

    // ldsm x4 lane offsets (16 rows x 16-bf16 cols)
    unsigned koff4 = (((lane & 7) + 8 * (lane >> 4)) * STRK + 8 * ((lane >> 3) & 1)) * 2;
    unsigned voff4 = (((lane & 7) + 8 * (lane >> 4)) * STRV + 8 * ((lane >> 3) & 1)) * 2;

    float oacc[8][4] = {};
    float lS0 = 0.f, lS1 = 0.f;

    for (int tt = 0; tt < ntiles; ++tt) {
        char* st = smem + (tt & 1) * STAGE;
        unsigned kbH = smem_u32(st) + OFF_KH, kbL = smem_u32(st) + OFF_KL;
        unsigned vbH = smem_u32(st) + OFF_VH, vbL = smem_u32(st) + OFF_VL;
        const float* djs = (const float*)(st + OFF_DJ);

        cp_wait<1>();
        __syncthreads();

        // ---- S = Q.K^T (log2 domain), 3-term bf16; K tile has 32 j rows ----
        float sacc[4][4];
#pragma unroll
        for (int j = 0; j < 4; j++)
#pragma unroll
            for (int e = 0; e < 4; e++) sacc[j][e] = 0.f;

#pragma unroll
        for (int c = 0; c < 4; c++) {
            unsigned kh[4][2], kl[4][2];
#pragma unroll
            for (int jp = 0; jp < 2; jp++) {
                unsigned r[4];
                unsigned a = koff4 + (jp * 16 * STRK + 16 * c) * 2;
                ldsm4(r, kbH + a);
                kh[2 * jp][0] = r[0]; kh[2 * jp][1] = r[1];
                kh[2 * jp + 1][0] = r[2]; kh[2 * jp + 1][1] = r[3];
                ldsm4(r, kbL + a);
                kl[2 * jp][0] = r[0]; kl[2 * jp][1] = r[1];
                kl[2 * jp + 1][0] = r[2]; kl[2 * jp + 1][1] = r[3];
            }
#pragma unroll
            for (int j = 0; j < 4; j++) mma_bf16(sacc[j], qfh[c], kh[j][0], kh[j][1]);
#pragma unroll
            for (int j = 0; j < 4; j++) mma_bf16(sacc[j], qfh[c], kl[j][0], kl[j][1]);
#pragma unroll
            for (int j = 0; j < 4; j++) mma_bf16(sacc[j], qfl[c], kh[j][0], kh[j][1]);
        }

        // ---- fixed-shift softmax: p = exp2(s + bias - FIXM) ----
#pragma unroll
        for (int j = 0; j < 4; j++) {
            float2 b = *(const float2*)&djs[8 * j + 2 * t4];
            float b0 = fmaf(slopeL, b.x, -FIXM);
            float b1 = fmaf(slopeL, b.y, -FIXM);
            sacc[j][0] = ex2(sacc[j][0] + b0);
            sacc[j][1] = ex2(sacc[j][1] + b1);
            sacc[j][2] = ex2(sacc[j][2] + b0);
            sacc[j][3] = ex2(sacc[j][3] + b1);
            lS0 += sacc[j][0] + sacc[j][1];
            lS1 += sacc[j][2] + sacc[j][3];
        }

        // ---- O += P.V (C->A identity); V^T tile 64 d-rows x 32 j-cols ----
#pragma unroll
        for (int c = 0; c < 2; c++) {   // k16 steps over j (KT=32)
            unsigned ph[4], pl[4];
            splitpack(sacc[2 * c][0],     sacc[2 * c][1],     ph[0], pl[0]);
            splitpack(sacc[2 * c][2],     sacc[2 * c][3],     ph[1], pl[1]);
            splitpack(sacc[2 * c + 1][0], sacc[2 * c + 1][1], ph[2], pl[2]);
            splitpack(sacc[2 * c + 1][2], sacc[2 * c + 1][3], ph[3], pl[3]);
            unsigned vh[8][2], vl[8][2];
#pragma unroll
            for (int jp = 0; jp < 4; jp++) {   // d-row groups of 16 (64 total)
                unsigned r[4];
                unsigned a = voff4 + (jp * 16 * STRV + 16 * c) * 2;
                ldsm4(r, vbH + a);
                vh[2 * jp][0] = r[0]; vh[2 * jp][1] = r[1];
                vh[2 * jp + 1][0] = r[2]; vh[2 * jp + 1][1] = r[3];
                ldsm4(r, vbL + a);
                vl[2 * jp][0] = r[0]; vl[2 * jp][1] = r[1];
                vl[2 * jp + 1][0] = r[2]; vl[2 * jp + 1][1] = r[3];
            }
#pragma unroll
            for (int dj = 0; dj < 8; dj++) mma_bf16(oacc[dj], ph, vh[dj][0], vh[dj][1]);
#pragma unroll
            for (int dj = 0; dj < 8; dj++) mma_bf16(oacc[dj], ph, vl[dj][0], vl[dj][1]);
#pragma unroll
            for (int dj = 0; dj < 8; dj++) mma_bf16(oacc[dj], pl, vh[dj][0], vh[dj][1]);
        }

        __syncthreads();   // stage fully consumed
        if (tt + 2 < ntiles) prefetch_tile(smem, tt & 1, h, (tt + 2) * KT, tid);
        cp_commit();
    }

    // ---- single end-of-kernel row-sum reduction (quad lanes share rows) ----
    lS0 += __shfl_xor_sync(0xffffffffu, lS0, 1);
    lS0 += __shfl_xor_sync(0xffffffffu, lS0, 2);
    lS1 += __shfl_xor_sync(0xffffffffu, lS1, 1);
    lS1 += __shfl_xor_sync(0xffffffffu, lS1, 2);
    float inv0 = 1.0f / lS0, inv1 = 1.0f / lS1;
    int r0 = q0 + 16 * w + g, r1 = r0 + 8;
    float* O0 = Out + ((size_t)h * SLEN + r0) * HD;
    float* O1 = Out + ((size_t)h * SLEN + r1) * HD;
#pragma unroll
    for (int dj = 0; dj < 8; dj++) {
        int col = 8 * dj + 2 * t4;
        *(float2*)&O0[col] = make_float2(oacc[dj][0] * inv0, oacc[dj][1] * inv0);
        *(float2*)&O1[col] = make_float2(oacc[dj][2] * inv1, oacc[dj][3] * inv1);
    }
}

// ---------------------------------------------------------------------------
extern "C" void kernel_launch(void* const* d_in, const int* in_sizes, int n_in,
                              void* d_out, int out_size) {
    const float*         Q    = (const float*)d_in[0];
    const float*         K    = (const float*)d_in[1];
    const float*         V    = (const float*)d_in[2];
    const unsigned char* mask = (const unsigned char*)d_in[3];
    float*               out  = (float*)d_out;

    cudaFuncSetAttribute(attn_kernel, cudaFuncAttributeMaxDynamicSharedMemorySize, SMEM_BYTES);

    compact_kernel<<<1, 256>>>(mask);
    dim3 gs(SLEN / 16, NH);
    scatter_kernel<<<gs, 256>>>(K, V);
    dim3 ga(SLEN / QT, NH);
    attn_kernel<<<ga, 128, SMEM_BYTES>>>(Q, out);
}

// round 13
// speedup vs baseline: 1.6455x; 1.0344x over previous
#include <cuda_runtime.h>
#include <cuda_bf16.h>

#define SLEN 2048
#define NH   16
#define HD   64
#define QT   128
#define KT   32
#define LOG2E 1.4426950408889634f
#define FIXM 12.0f

// smem stage layout (KT=32): K tiles 32x72 bf16, V^T tiles 64x40 bf16
#define STRK 72
#define STRV 40
#define OFF_KH 0
#define OFF_KL 4608
#define OFF_VH 9216
#define OFF_VL 14336
#define OFF_DJ 19456
#define STAGE  19584
#define SMEM_BYTES (2 * STAGE)   // 39168

// Scratch (allocation-free rule) — layouts identical to R7/R12
__device__ __nv_bfloat16 g_Kh [NH * SLEN * HD];   // K rows [h][j][d], hi
__device__ __nv_bfloat16 g_Kl [NH * SLEN * HD];
__device__ __nv_bfloat16 g_VtH[NH * HD * SLEN];   // V transposed [h][d][j]
__device__ __nv_bfloat16 g_VtL[NH * HD * SLEN];
__device__ float g_posf[SLEN];
__device__ int   g_pos [SLEN];
__device__ int   g_nvalid;

// ---- helpers ----------------------------------------------------------------
__device__ __forceinline__ unsigned smem_u32(const void* p) {
    return (unsigned)__cvta_generic_to_shared(p);
}
__device__ __forceinline__ float ex2(float x) {
    float r; asm("ex2.approx.f32 %0, %1;" : "=f"(r) : "f"(x)); return r;
}
__device__ __forceinline__ void splitpack(float x0, float x1, unsigned& hp, unsigned& lp) {
    __nv_bfloat16 h0 = __float2bfloat16(x0), h1 = __float2bfloat16(x1);
    float r0 = x0 - __bfloat162float(h0), r1 = x1 - __bfloat162float(h1);
    __nv_bfloat16 l0 = __float2bfloat16(r0), l1 = __float2bfloat16(r1);
    hp = ((unsigned)__bfloat16_as_ushort(h1) << 16) | (unsigned)__bfloat16_as_ushort(h0);
    lp = ((unsigned)__bfloat16_as_ushort(l1) << 16) | (unsigned)__bfloat16_as_ushort(l0);
}
__device__ __forceinline__ void cp16(unsigned dst, const void* src) {
    asm volatile("cp.async.cg.shared.global [%0], [%1], 16;" :: "r"(dst), "l"(src));
}
__device__ __forceinline__ void cp_commit() { asm volatile("cp.async.commit_group;"); }
template<int N> __device__ __forceinline__ void cp_wait() {
    asm volatile("cp.async.wait_group %0;" :: "n"(N));
}
__device__ __forceinline__ void mma_bf16(float (&d)[4], const unsigned (&a)[4],
                                         unsigned b0, unsigned b1) {
    asm("mma.sync.aligned.m16n8k16.row.col.f32.bf16.bf16.f32 "
        "{%0,%1,%2,%3}, {%4,%5,%6,%7}, {%8,%9}, {%0,%1,%2,%3};"
        : "+f"(d[0]), "+f"(d[1]), "+f"(d[2]), "+f"(d[3])
        : "r"(a[0]), "r"(a[1]), "r"(a[2]), "r"(a[3]), "r"(b0), "r"(b1));
}
__device__ __forceinline__ void ldsm4(unsigned (&r)[4], unsigned addr) {
    asm volatile("ldmatrix.sync.aligned.m8n8.x4.shared.b16 {%0,%1,%2,%3}, [%4];"
        : "=r"(r[0]), "=r"(r[1]), "=r"(r[2]), "=r"(r[3]) : "r"(addr));
}

// ---------------------------------------------------------------------------
// Kernel 1: mask compaction (unchanged — proven)
// ---------------------------------------------------------------------------
__global__ void compact_kernel(const unsigned char* __restrict__ mask8) {
    __shared__ int warpSum[8];
    int tid  = threadIdx.x;
    int lane = tid & 31, wid = tid >> 5;
    int base = tid * 8;
    int probe = 0;
#pragma unroll
    for (int i = 0; i < 8; i++) {
        int p = base + i;
        if ((p & 3) != 0 && mask8[p] != 0) probe = 1;
    }
    int isU8 = __syncthreads_or(probe);
    const int* mask32 = (const int*)mask8;
    int v[8], c = 0;
#pragma unroll
    for (int i = 0; i < 8; i++) {
        int e = base + i;
        int val = isU8 ? (int)(mask8[e] != 0) : (int)(mask32[e] != 0);
        v[i] = val; c += val;
    }
    int incl = c;
#pragma unroll
    for (int off = 1; off < 32; off <<= 1) {
        int t = __shfl_up_sync(0xffffffffu, incl, off);
        if (lane >= off) incl += t;
    }
    if (lane == 31) warpSum[wid] = incl;
    __syncthreads();
    if (wid == 0) {
        int ws = (lane < 8) ? warpSum[lane] : 0;
#pragma unroll
        for (int off = 1; off < 8; off <<= 1) {
            int t = __shfl_up_sync(0xffffffffu, ws, off);
            if (lane >= off) ws += t;
        }
        if (lane < 8) warpSum[lane] = ws;
    }
    __syncthreads();
    int wbase = (wid > 0) ? warpSum[wid - 1] : 0;
    int idx = wbase + incl - c;
#pragma unroll
    for (int i = 0; i < 8; i++) {
        if (v[i]) {
            g_pos [idx] = base + i;
            g_posf[idx] = (float)(base + i - (SLEN - 1));
            idx++;
        }
    }
    int n = warpSum[7];
    for (int j = n + tid; j < SLEN; j += 256) g_posf[j] = -1.0e30f;
    if (tid == 0) g_nvalid = n;
}

// ---------------------------------------------------------------------------
// Kernel 2: gather + hi/lo split (unchanged — proven)
// ---------------------------------------------------------------------------
__global__ void scatter_kernel(const float* __restrict__ K, const float* __restrict__ V) {
    int h   = blockIdx.y;
    int jin = threadIdx.x & 15;
    int d4  = threadIdx.x >> 4;
    int j   = blockIdx.x * 16 + jin;
    int n   = g_nvalid;
    float4 kk = make_float4(0.f, 0.f, 0.f, 0.f), vv = kk;
    if (j < n) {
        int src = g_pos[j];
        kk = *(const float4*)(K + ((size_t)h * SLEN + src) * HD + d4 * 4);
        vv = *(const float4*)(V + ((size_t)h * SLEN + src) * HD + d4 * 4);
    }
    float ka[4] = {kk.x, kk.y, kk.z, kk.w};
    float va[4] = {vv.x, vv.y, vv.z, vv.w};
    size_t kbase = ((size_t)h * SLEN + j) * HD + 4 * d4;
#pragma unroll
    for (int e = 0; e < 4; e++) {
        __nv_bfloat16 hh = __float2bfloat16(ka[e]);
        __nv_bfloat16 ll = __float2bfloat16(ka[e] - __bfloat162float(hh));
        g_Kh[kbase + e] = hh;
        g_Kl[kbase + e] = ll;
        __nv_bfloat16 vh = __float2bfloat16(va[e]);
        __nv_bfloat16 vl = __float2bfloat16(va[e] - __bfloat162float(vh));
        size_t vt = ((size_t)h * HD + 4 * d4 + e) * SLEN + j;
        g_VtH[vt] = vh;
        g_VtL[vt] = vl;
    }
}

// ---------------------------------------------------------------------------
// prefetch one KT=32 K/V tile (+djs) into a stage via cp.async (R12, proven)
// ---------------------------------------------------------------------------
__device__ __forceinline__ void prefetch_tile(char* smem, int stage, int h, int k0, int tid) {
    unsigned st = smem_u32(smem + stage * STAGE);
    const char* bKh = (const char*)(g_Kh + ((size_t)h * SLEN + k0) * HD);
    const char* bKl = (const char*)(g_Kl + ((size_t)h * SLEN + k0) * HD);
#pragma unroll
    for (int i = 0; i < 2; i++) {   // K hi/lo: 256 chunks each (8 per 128B row)
        int idx = tid + 128 * i;
        int row = idx >> 3, c = idx & 7;
        unsigned off = row * (STRK * 2) + c * 16;
        cp16(st + OFF_KH + off, bKh + idx * 16);
        cp16(st + OFF_KL + off, bKl + idx * 16);
    }
#pragma unroll
    for (int i = 0; i < 2; i++) {   // V hi/lo: 256 chunks each (4 per 64B row)
        int idx = tid + 128 * i;
        int row = idx >> 2, c = idx & 3;
        unsigned off = row * (STRV * 2) + c * 16;
        cp16(st + OFF_VH + off, (const char*)(g_VtH + ((size_t)h * HD + row) * SLEN + k0) + c * 16);
        cp16(st + OFF_VL + off, (const char*)(g_VtL + ((size_t)h * HD + row) * SLEN + k0) + c * 16);
    }
    if (tid < 8) cp16(st + OFF_DJ + tid * 16, (const char*)(g_posf + k0) + tid * 16);
}

// ---------------------------------------------------------------------------
// Kernel 3: flash attention, mma.sync, QT=128 (2 q-groups per warp) to halve
// ldsm traffic per mma. 256 CTAs, 2 CTAs/SM, single wave.
// Warp w owns rows {16w..16w+15} (group 0) and {64+16w..} (group 1).
// ---------------------------------------------------------------------------
__global__ __launch_bounds__(128, 2) void attn_kernel(const float* __restrict__ Q,
                                                      float* __restrict__ Out) {
    extern __shared__ char smem[];
    int tid = threadIdx.x, w = tid >> 5, lane = tid & 31;
    int t4 = lane & 3, g = lane >> 2;
    int h = blockIdx.y, q0 = blockIdx.x * QT;
    const float scaleL = 0.125f * LOG2E;
    const float slopeL = exp2f(-0.5f * (float)(h + 1)) * LOG2E;
    int n = g_nvalid, ntiles = (n + KT - 1) >> 5;

    prefetch_tile(smem, 0, h, 0, tid);
    cp_commit();

    // ---- Q prologue: two 64-row halves staged through stage-1 region ----
    __nv_bfloat16* Qh = (__nv_bfloat16*)(smem + STAGE);
    __nv_bfloat16* Ql = Qh + 64 * STRK;
    unsigned qbH = smem_u32(Qh), qbL = smem_u32(Ql);
    unsigned qoff = ((16 * w + (lane & 15)) * STRK + 8 * (lane >> 4)) * 2;
    unsigned qfh[2][4][4], qfl[2][4][4];
#pragma unroll
    for (int gi = 0; gi < 2; gi++) {
        const float* Qg = Q + ((size_t)h * SLEN + q0 + gi * 64) * HD;
        for (int idx = tid; idx < 64 * 16; idx += 128) {
            int row = idx >> 4, c4 = idx & 15;
            float4 v = *(const float4*)(Qg + row * HD + c4 * 4);
            unsigned hp0, lp0, hp1, lp1;
            splitpack(v.x * scaleL, v.y * scaleL, hp0, lp0);
            splitpack(v.z * scaleL, v.w * scaleL, hp1, lp1);
            unsigned off = row * STRK + 4 * c4;
            *(unsigned*)&Qh[off]     = hp0;
            *(unsigned*)&Qh[off + 2] = hp1;
            *(unsigned*)&Ql[off]     = lp0;
            *(unsigned*)&Ql[off + 2] = lp1;
        }
        __syncthreads();
#pragma unroll
        for (int c = 0; c < 4; c++) {
            ldsm4(qfh[gi][c], qbH + qoff + 32 * c);
            ldsm4(qfl[gi][c], qbL + qoff + 32 * c);
        }
        __syncthreads();   // staging free for next half / stage-1 prefetch
    }

    if (ntiles > 1) prefetch_tile(smem, 1, h, KT, tid);
    cp_commit();

    unsigned koff4 = (((lane & 7) + 8 * (lane >> 4)) * STRK + 8 * ((lane >> 3) & 1)) * 2;
    unsigned voff4 = (((lane & 7) + 8 * (lane >> 4)) * STRV + 8 * ((lane >> 3) & 1)) * 2;

    float oacc[2][8][4] = {};
    float lS[2][2] = {};

    for (int tt = 0; tt < ntiles; ++tt) {
        char* st = smem + (tt & 1) * STAGE;
        unsigned kbH = smem_u32(st) + OFF_KH, kbL = smem_u32(st) + OFF_KL;
        unsigned vbH = smem_u32(st) + OFF_VH, vbL = smem_u32(st) + OFF_VL;
        const float* djs = (const float*)(st + OFF_DJ);

        cp_wait<1>();
        __syncthreads();

        // ---- S = Q.K^T (log2 domain), 3-term bf16, both q-groups per K frag ----
        float sacc[2][4][4];
#pragma unroll
        for (int gi = 0; gi < 2; gi++)
#pragma unroll
            for (int j = 0; j < 4; j++)
#pragma unroll
                for (int e = 0; e < 4; e++) sacc[gi][j][e] = 0.f;

#pragma unroll
        for (int c = 0; c < 4; c++) {
            unsigned kh[4][2], kl[4][2];
#pragma unroll
            for (int jp = 0; jp < 2; jp++) {
                unsigned r[4];
                unsigned a = koff4 + (jp * 16 * STRK + 16 * c) * 2;
                ldsm4(r, kbH + a);
                kh[2 * jp][0] = r[0]; kh[2 * jp][1] = r[1];
                kh[2 * jp + 1][0] = r[2]; kh[2 * jp + 1][1] = r[3];
                ldsm4(r, kbL + a);
                kl[2 * jp][0] = r[0]; kl[2 * jp][1] = r[1];
                kl[2 * jp + 1][0] = r[2]; kl[2 * jp + 1][1] = r[3];
            }
#pragma unroll
            for (int gi = 0; gi < 2; gi++) {
#pragma unroll
                for (int j = 0; j < 4; j++) mma_bf16(sacc[gi][j], qfh[gi][c], kh[j][0], kh[j][1]);
#pragma unroll
                for (int j = 0; j < 4; j++) mma_bf16(sacc[gi][j], qfh[gi][c], kl[j][0], kl[j][1]);
#pragma unroll
                for (int j = 0; j < 4; j++) mma_bf16(sacc[gi][j], qfl[gi][c], kh[j][0], kh[j][1]);
            }
        }

        // ---- fixed-shift softmax + P splitpack (frees sacc before V loads) ----
        unsigned phA[2][2][4], plA[2][2][4];
#pragma unroll
        for (int gi = 0; gi < 2; gi++) {
#pragma unroll
            for (int j = 0; j < 4; j++) {
                float2 b = *(const float2*)&djs[8 * j + 2 * t4];
                float b0 = fmaf(slopeL, b.x, -FIXM);
                float b1 = fmaf(slopeL, b.y, -FIXM);
                float p0 = ex2(sacc[gi][j][0] + b0);
                float p1 = ex2(sacc[gi][j][1] + b1);
                float p2 = ex2(sacc[gi][j][2] + b0);
                float p3 = ex2(sacc[gi][j][3] + b1);
                lS[gi][0] += p0 + p1;
                lS[gi][1] += p2 + p3;
                int c = j >> 1, f = (j & 1) * 2;
                splitpack(p0, p1, phA[gi][c][f],     plA[gi][c][f]);
                splitpack(p2, p3, phA[gi][c][f + 1], plA[gi][c][f + 1]);
            }
        }

        // ---- O += P.V; V frags loaded once, feed both q-groups ----
#pragma unroll
        for (int c = 0; c < 2; c++) {
            unsigned vh[8][2], vl[8][2];
#pragma unroll
            for (int jp = 0; jp < 4; jp++) {
                unsigned r[4];
                unsigned a = voff4 + (jp * 16 * STRV + 16 * c) * 2;
                ldsm4(r, vbH + a);
                vh[2 * jp][0] = r[0]; vh[2 * jp][1] = r[1];
                vh[2 * jp + 1][0] = r[2]; vh[2 * jp + 1][1] = r[3];
                ldsm4(r, vbL + a);
                vl[2 * jp][0] = r[0]; vl[2 * jp][1] = r[1];
                vl[2 * jp + 1][0] = r[2]; vl[2 * jp + 1][1] = r[3];
            }
#pragma unroll
            for (int gi = 0; gi < 2; gi++) {
#pragma unroll
                for (int dj = 0; dj < 8; dj++) mma_bf16(oacc[gi][dj], phA[gi][c], vh[dj][0], vh[dj][1]);
#pragma unroll
                for (int dj = 0; dj < 8; dj++) mma_bf16(oacc[gi][dj], phA[gi][c], vl[dj][0], vl[dj][1]);
#pragma unroll
                for (int dj = 0; dj < 8; dj++) mma_bf16(oacc[gi][dj], plA[gi][c], vh[dj][0], vh[dj][1]);
            }
        }

        __syncthreads();   // stage fully consumed
        if (tt + 2 < ntiles) prefetch_tile(smem, tt & 1, h, (tt + 2) * KT, tid);
        cp_commit();
    }

    // ---- epilogue: per-group row-sum reduction + store ----
#pragma unroll
    for (int gi = 0; gi < 2; gi++) {
        float l0 = lS[gi][0], l1 = lS[gi][1];
        l0 += __shfl_xor_sync(0xffffffffu, l0, 1);
        l0 += __shfl_xor_sync(0xffffffffu, l0, 2);
        l1 += __shfl_xor_sync(0xffffffffu, l1, 1);
        l1 += __shfl_xor_sync(0xffffffffu, l1, 2);
        float inv0 = 1.0f / l0, inv1 = 1.0f / l1;
        int r0 = q0 + gi * 64 + 16 * w + g, r1 = r0 + 8;
        float* O0 = Out + ((size_t)h * SLEN + r0) * HD;
        float* O1 = Out + ((size_t)h * SLEN + r1) * HD;
#pragma unroll
        for (int dj = 0; dj < 8; dj++) {
            int col = 8 * dj + 2 * t4;
            *(float2*)&O0[col] = make_float2(oacc[gi][dj][0] * inv0, oacc[gi][dj][1] * inv0);
            *(float2*)&O1[col] = make_float2(oacc[gi][dj][2] * inv1, oacc[gi][dj][3] * inv1);
        }
    }
}

// ---------------------------------------------------------------------------
extern "C" void kernel_launch(void* const* d_in, const int* in_sizes, int n_in,
                              void* d_out, int out_size) {
    const float*         Q    = (const float*)d_in[0];
    const float*         K    = (const float*)d_in[1];
    const float*         V    = (const float*)d_in[2];
    const unsigned char* mask = (const unsigned char*)d_in[3];
    float*               out  = (float*)d_out;

    cudaFuncSetAttribute(attn_kernel, cudaFuncAttributeMaxDynamicSharedMemorySize, SMEM_BYTES);

    compact_kernel<<<1, 256>>>(mask);
    dim3 gs(SLEN / 16, NH);
    scatter_kernel<<<gs, 256>>>(K, V);
    dim3 ga(SLEN / QT, NH);
    attn_kernel<<<ga, 128, SMEM_BYTES>>>(Q, out);
}